// round 8
// baseline (speedup 1.0000x reference)
#include <cuda_runtime.h>
#include <cuda_fp16.h>
#include <cstdint>

// Path_Embedding via mma.sync m16n8k16.f16, single-f16 operands.
// Round 8: persistent blocks (592 = 4/SM, one wave), W staged once per block,
// m32xn32 warp tiles (2.0 MMA per ldmatrix.x4), 2-sync pipelined tile loop
// (idx prefetch under MMA, output store overlapped with next gather,
// double-buffered reduction scratch).

#define VOCAB 100000
#define NPERS 592
#define RSE 160        // e-row stride bytes (+16B nudge when a odd)
#define RSW 144        // w-row stride bytes (+16B nudge when (o>>3)&1)

#define E_OFF   0      // 160*160 = 25600
#define W_OFF   25600  // 2 taps * 64 * 144 = 18432
#define IDX_OFF 44032  // 160*4
#define RED_OFF 44672  // 2*8*32*4 = 2048
#define SM_TOT  46720

typedef unsigned long long u64;

__device__ __forceinline__ uint32_t smem_u32(const void* p) {
    uint32_t a;
    asm("{ .reg .u64 t; cvta.to.shared.u64 t, %1; cvt.u32.u64 %0, t; }" : "=r"(a) : "l"(p));
    return a;
}

#define LDMX4(r, addr)                                                        \
    asm volatile("ldmatrix.sync.aligned.m8n8.x4.shared.b16 {%0,%1,%2,%3}, [%4];" \
        : "=r"((r)[0]), "=r"((r)[1]), "=r"((r)[2]), "=r"((r)[3]) : "r"(addr))

#define MMA(d, a, b0, b1)                                                     \
    asm volatile("mma.sync.aligned.m16n8k16.row.col.f32.f16.f16.f32 "         \
        "{%0,%1,%2,%3},{%4,%5,%6,%7},{%8,%9},{%0,%1,%2,%3};"                  \
        : "+f"((d)[0]), "+f"((d)[1]), "+f"((d)[2]), "+f"((d)[3])              \
        : "r"((a)[0]), "r"((a)[1]), "r"((a)[2]), "r"((a)[3]),                 \
          "r"(b0), "r"(b1))

__device__ __forceinline__ u64 pack4(float x, float y, float z, float w) {
    __half2 h01 = __float22half2_rn(make_float2(x, y));
    __half2 h23 = __float22half2_rn(make_float2(z, w));
    uint32_t h0 = *reinterpret_cast<uint32_t*>(&h01);
    uint32_t h1 = *reinterpret_cast<uint32_t*>(&h23);
    return (u64)h0 | ((u64)h1 << 32);
}

__global__ __launch_bounds__(256, 4) void path_emb_hmma(
    const int*   __restrict__ path_input,   // [8192,16,5]
    const int*   __restrict__ path_type,    // [5]
    const float* __restrict__ tables,       // [3,100000,64]
    const float* __restrict__ conv_w,       // [64,64,2]
    const float* __restrict__ conv_b,       // [64]
    float*       __restrict__ out)          // [8192,64]
{
    extern __shared__ char smem[];
    const uint32_t sb = smem_u32(smem);
    const int tid  = threadIdx.x;
    const int lane = tid & 31;
    const int wid  = tid >> 5;
    const int mgrp = wid & 3;                // m0 = mgrp*32
    const int ngrp = wid >> 2;               // n0 = ngrp*32

    int*  idx_s = reinterpret_cast<int*>(smem + IDX_OFF);
    float (*red)[8][32] = reinterpret_cast<float(*)[8][32]>(smem + RED_OFF);

    // ---- stage W once per block: [tap][o][k64], stride 144B + nudge ----
    {
        const float2* cw2 = reinterpret_cast<const float2*>(conv_w);
        #pragma unroll
        for (int it = 0; it < 16; it++) {
            int i = tid + it * 256;          // i = o*64 + j
            int o = i >> 6, j = i & 63;
            float2 wv = cw2[i];              // (W0[o][j], W1[o][j])
            int ob = o * RSW + (((o >> 3) & 1) << 4) + j * 2;
            *reinterpret_cast<__half*>(smem + W_OFF + ob)        = __float2half_rn(wv.x);
            *reinterpret_cast<__half*>(smem + W_OFF + 9216 + ob) = __float2half_rn(wv.y);
        }
    }

    // ---- per-warp ldmatrix lane addresses (tile-invariant) ----
    uint32_t ab0, ab1, bb0, bb1;
    {
        int m  = mgrp * 32 + (lane & 15);
        int b2 = mgrp >> 1;
        int aa = (m >> 2) & 15, w = m & 3;
        ab0 = (uint32_t)((b2 * 80 + aa * 5 + w) * RSE + ((aa & 1) << 4)
                         + ((lane >> 4) << 4));
        int m1 = m + 16;
        int aa1 = (m1 >> 2) & 15, w1 = m1 & 3;
        ab1 = (uint32_t)((b2 * 80 + aa1 * 5 + w1) * RSE + ((aa1 & 1) << 4)
                         + ((lane >> 4) << 4));
        int nr = ngrp * 32 + (lane & 7) + ((lane >> 4) << 3);
        bb0 = (uint32_t)(nr * RSW + (((nr >> 3) & 1) << 4) + (((lane >> 3) & 1) << 4));
        int nr1 = nr + 16;
        bb1 = (uint32_t)(nr1 * RSW + (((nr1 >> 3) & 1) << 4) + (((lane >> 3) & 1) << 4));
    }

    // ---- stage indices for the first tile ----
    int tile = blockIdx.x;
    if (tid < 160) {
        int b2 = tid / 80, rr = tid % 80, a = rr / 5, t = rr % 5;
        int b = tile * 2 + b2, p = b & 15, nb = b >> 4;
        int raw = path_input[(((a << 9) + nb) * 16 + p) * 5 + t];
        idx_s[tid] = __ldg(&path_type[t]) * VOCAB + raw;
    }
    __syncthreads();

    const float4* tab4 = reinterpret_cast<const float4*>(tables);
    int par = 0, prev = -1;

    for (; tile < 4096; tile += NPERS) {
        // ================= phase A: gather E(tile) + store out(prev) ========
        #pragma unroll
        for (int g = 0; g < 10; g++) {
            int k = tid + g * 256;
            int row = k >> 4, q = k & 15;
            float4 v = __ldg(&tab4[(long long)idx_s[row] * 16 + q]);
            int a = (row % 80) / 5;
            int off = row * RSE + ((a & 1) << 4) + q * 8;
            *reinterpret_cast<u64*>(smem + E_OFF + off) = pack4(v.x, v.y, v.z, v.w);
        }
        if (prev >= 0 && tid < 128) {
            int b2 = tid >> 6, c = tid & 63, ch = c >> 5, cc = c & 31;
            int w1 = ch * 4 + b2 * 2;
            float m = fmaxf(red[par ^ 1][w1][cc], red[par ^ 1][w1 + 1][cc]);
            out[(long long)(prev * 2 + b2) * 64 + c] = m + __ldg(&conv_b[c]);
        }
        __syncthreads();

        // ================= phase B: prefetch idx(t+NPERS), mma, red-store ===
        if (tid < 160 && tile + NPERS < 4096) {
            int nt = tile + NPERS;
            int b2 = tid / 80, rr = tid % 80, a = rr / 5, t = rr % 5;
            int b = nt * 2 + b2, p = b & 15, nb = b >> 4;
            int raw = path_input[(((a << 9) + nb) * 16 + p) * 5 + t];
            idx_s[tid] = __ldg(&path_type[t]) * VOCAB + raw;
        }

        float d[2][4][4];
        #pragma unroll
        for (int mt = 0; mt < 2; mt++)
            #pragma unroll
            for (int nt = 0; nt < 4; nt++)
                #pragma unroll
                for (int r = 0; r < 4; r++) d[mt][nt][r] = 0.f;

        #pragma unroll
        for (int tap = 0; tap < 2; tap++) {
            const uint32_t aE0 = sb + E_OFF + ab0 + tap * RSE;
            const uint32_t aE1 = sb + E_OFF + ab1 + tap * RSE;
            const uint32_t bW0 = sb + W_OFF + tap * 9216 + bb0;
            const uint32_t bW1 = sb + W_OFF + tap * 9216 + bb1;
            #pragma unroll
            for (int ks = 0; ks < 4; ks++) {
                const uint32_t kb = ks * 32;
                uint32_t a0[4], a1[4], b0[4], b1[4];
                LDMX4(a0, aE0 + kb);
                LDMX4(a1, aE1 + kb);
                LDMX4(b0, bW0 + kb);
                LDMX4(b1, bW1 + kb);
                MMA(d[0][0], a0, b0[0], b0[1]);
                MMA(d[0][1], a0, b0[2], b0[3]);
                MMA(d[0][2], a0, b1[0], b1[1]);
                MMA(d[0][3], a0, b1[2], b1[3]);
                MMA(d[1][0], a1, b0[0], b0[1]);
                MMA(d[1][1], a1, b0[2], b0[3]);
                MMA(d[1][2], a1, b1[0], b1[1]);
                MMA(d[1][3], a1, b1[2], b1[3]);
            }
        }

        // max over this warp's 32 m-rows per column -> red[par][wid][0:32]
        #pragma unroll
        for (int nt = 0; nt < 4; nt++) {
            float v0 = fmaxf(fmaxf(d[0][nt][0], d[0][nt][2]),
                             fmaxf(d[1][nt][0], d[1][nt][2]));
            float v1 = fmaxf(fmaxf(d[0][nt][1], d[0][nt][3]),
                             fmaxf(d[1][nt][1], d[1][nt][3]));
            #pragma unroll
            for (int mask = 4; mask <= 16; mask <<= 1) {
                v0 = fmaxf(v0, __shfl_xor_sync(0xffffffffu, v0, mask));
                v1 = fmaxf(v1, __shfl_xor_sync(0xffffffffu, v1, mask));
            }
            if (lane < 4) {
                red[par][wid][nt * 8 + lane * 2]     = v0;
                red[par][wid][nt * 8 + lane * 2 + 1] = v1;
            }
        }
        __syncthreads();

        prev = tile;
        par ^= 1;
    }

    // ---- flush last tile's output ----
    if (prev >= 0 && tid < 128) {
        int b2 = tid >> 6, c = tid & 63, ch = c >> 5, cc = c & 31;
        int w1 = ch * 4 + b2 * 2;
        float m = fmaxf(red[par ^ 1][w1][cc], red[par ^ 1][w1 + 1][cc]);
        out[(long long)(prev * 2 + b2) * 64 + c] = m + __ldg(&conv_b[c]);
    }
}

extern "C" void kernel_launch(void* const* d_in, const int* in_sizes, int n_in,
                              void* d_out, int out_size) {
    const int*   path_input = (const int*)d_in[0];
    const int*   path_type  = (const int*)d_in[1];
    const float* tables     = (const float*)d_in[2];
    const float* conv_w     = (const float*)d_in[3];
    const float* conv_b     = (const float*)d_in[4];
    float* out = (float*)d_out;

    cudaFuncSetAttribute(path_emb_hmma,
                         cudaFuncAttributeMaxDynamicSharedMemorySize, SM_TOT);

    path_emb_hmma<<<NPERS, 256, SM_TOT>>>(path_input, path_type, tables,
                                          conv_w, conv_b, out);
}

// round 9
// speedup vs baseline: 1.1577x; 1.1577x over previous
#include <cuda_runtime.h>
#include <cuda_fp16.h>
#include <cstdint>

// Path_Embedding via mma.sync m16n8k16.f16, single-f16 operands.
// Round 9: persistent blocks (444 = 3/SM), software pipeline with the next
// tile's gather held IN REGISTERS across the MMA phase (DRAM latency hidden
// under tensor work); E single-buffered (stores happen after all MMA reads).

#define VOCAB 100000
#define NPERS 444
#define RSE 160        // e-row stride bytes (+16B nudge when a odd)
#define RSW 144        // w-row stride bytes (+16B nudge when (o>>3)&1)

#define E_OFF   0      // 160*160 = 25600
#define W_OFF   25600  // 2 taps * 64 * 144 = 18432
#define IDX_OFF 44032  // 160*4
#define RED_OFF 44672  // 2*8*32*4 = 2048
#define SM_TOT  46720

typedef unsigned long long u64;

__device__ __forceinline__ uint32_t smem_u32(const void* p) {
    uint32_t a;
    asm("{ .reg .u64 t; cvta.to.shared.u64 t, %1; cvt.u32.u64 %0, t; }" : "=r"(a) : "l"(p));
    return a;
}

#define LDMX4(r, addr)                                                        \
    asm volatile("ldmatrix.sync.aligned.m8n8.x4.shared.b16 {%0,%1,%2,%3}, [%4];" \
        : "=r"((r)[0]), "=r"((r)[1]), "=r"((r)[2]), "=r"((r)[3]) : "r"(addr))

#define MMA(d, a, b0, b1)                                                     \
    asm volatile("mma.sync.aligned.m16n8k16.row.col.f32.f16.f16.f32 "         \
        "{%0,%1,%2,%3},{%4,%5,%6,%7},{%8,%9},{%0,%1,%2,%3};"                  \
        : "+f"((d)[0]), "+f"((d)[1]), "+f"((d)[2]), "+f"((d)[3])              \
        : "r"((a)[0]), "r"((a)[1]), "r"((a)[2]), "r"((a)[3]),                 \
          "r"(b0), "r"(b1))

__device__ __forceinline__ u64 pack4(float x, float y, float z, float w) {
    __half2 h01 = __float22half2_rn(make_float2(x, y));
    __half2 h23 = __float22half2_rn(make_float2(z, w));
    uint32_t h0 = *reinterpret_cast<uint32_t*>(&h01);
    uint32_t h1 = *reinterpret_cast<uint32_t*>(&h23);
    return (u64)h0 | ((u64)h1 << 32);
}

__global__ __launch_bounds__(256, 3) void path_emb_hmma(
    const int*   __restrict__ path_input,   // [8192,16,5]
    const int*   __restrict__ path_type,    // [5]
    const float* __restrict__ tables,       // [3,100000,64]
    const float* __restrict__ conv_w,       // [64,64,2]
    const float* __restrict__ conv_b,       // [64]
    float*       __restrict__ out)          // [8192,64]
{
    extern __shared__ char smem[];
    const uint32_t sb = smem_u32(smem);
    const int tid  = threadIdx.x;
    const int lane = tid & 31;
    const int wid  = tid >> 5;
    const int mgrp = wid & 3;                // m0 = mgrp*32
    const int ngrp = wid >> 2;               // n0 = ngrp*32

    int*  idx_s = reinterpret_cast<int*>(smem + IDX_OFF);
    float (*red)[8][32] = reinterpret_cast<float(*)[8][32]>(smem + RED_OFF);
    const float4* tab4 = reinterpret_cast<const float4*>(tables);

    // ---- stage W once per block ----
    {
        const float2* cw2 = reinterpret_cast<const float2*>(conv_w);
        #pragma unroll
        for (int it = 0; it < 16; it++) {
            int i = tid + it * 256;          // i = o*64 + j
            int o = i >> 6, j = i & 63;
            float2 wv = cw2[i];
            int ob = o * RSW + (((o >> 3) & 1) << 4) + j * 2;
            *reinterpret_cast<__half*>(smem + W_OFF + ob)        = __float2half_rn(wv.x);
            *reinterpret_cast<__half*>(smem + W_OFF + 9216 + ob) = __float2half_rn(wv.y);
        }
    }

    // ---- ldmatrix lane addresses (tile-invariant) ----
    uint32_t ab0, ab1, bb0, bb1;
    {
        int m  = mgrp * 32 + (lane & 15);
        int b2 = mgrp >> 1;
        int aa = (m >> 2) & 15, w = m & 3;
        ab0 = (uint32_t)((b2 * 80 + aa * 5 + w) * RSE + ((aa & 1) << 4)
                         + ((lane >> 4) << 4));
        int m1 = m + 16;
        int aa1 = (m1 >> 2) & 15, w1 = m1 & 3;
        ab1 = (uint32_t)((b2 * 80 + aa1 * 5 + w1) * RSE + ((aa1 & 1) << 4)
                         + ((lane >> 4) << 4));
        int nr = ngrp * 32 + (lane & 7) + ((lane >> 4) << 3);
        bb0 = (uint32_t)(nr * RSW + (((nr >> 3) & 1) << 4) + (((lane >> 3) & 1) << 4));
        int nr1 = nr + 16;
        bb1 = (uint32_t)(nr1 * RSW + (((nr1 >> 3) & 1) << 4) + (((lane >> 3) & 1) << 4));
    }

    // ---- prologue: E(tile0) staged, idx_s = idx(tile0 + NPERS) ----
    const int tile0 = blockIdx.x;
    if (tid < 160) {
        int b2 = tid / 80, rr = tid % 80, a = rr / 5, t = rr % 5;
        int b = tile0 * 2 + b2, p = b & 15, nb = b >> 4;
        idx_s[tid] = __ldg(&path_type[t]) * VOCAB
                   + path_input[(((a << 9) + nb) * 16 + p) * 5 + t];
    }
    __syncthreads();
    #pragma unroll
    for (int g = 0; g < 10; g++) {
        int k = tid + g * 256, row = k >> 4, q = k & 15;
        float4 v = __ldg(&tab4[(long long)idx_s[row] * 16 + q]);
        int a = (row % 80) / 5;
        *reinterpret_cast<u64*>(smem + E_OFF + row * RSE + ((a & 1) << 4) + q * 8)
            = pack4(v.x, v.y, v.z, v.w);
    }
    __syncthreads();
    if (tid < 160 && tile0 + NPERS < 4096) {
        int nt = tile0 + NPERS;
        int b2 = tid / 80, rr = tid % 80, a = rr / 5, t = rr % 5;
        int b = nt * 2 + b2, p = b & 15, nb = b >> 4;
        idx_s[tid] = __ldg(&path_type[t]) * VOCAB
                   + path_input[(((a << 9) + nb) * 16 + p) * 5 + t];
    }
    __syncthreads();

    int par = 0;
    for (int tile = tile0; tile < 4096; tile += NPERS) {
        const bool nx  = tile + NPERS     < 4096;
        const bool nx2 = tile + 2 * NPERS < 4096;

        // ---- 1. issue next tile's gather LDGs; keep raw in registers ----
        float4 v[10];
        if (nx) {
            #pragma unroll
            for (int g = 0; g < 10; g++) {
                int k = tid + g * 256, row = k >> 4, q = k & 15;
                v[g] = __ldg(&tab4[(long long)idx_s[row] * 16 + q]);
            }
        }
        // ---- 2. prefetch idx(tile+2*NPERS) into a register ----
        int ridx = 0;
        if (tid < 160 && nx2) {
            int nt = tile + 2 * NPERS;
            int b2 = tid / 80, rr = tid % 80, a = rr / 5, t = rr % 5;
            int b = nt * 2 + b2, p = b & 15, nb = b >> 4;
            ridx = __ldg(&path_type[t]) * VOCAB
                 + path_input[(((a << 9) + nb) * 16 + p) * 5 + t];
        }

        // ---- 3. MMA on current E ----
        float d[2][4][4];
        #pragma unroll
        for (int mt = 0; mt < 2; mt++)
            #pragma unroll
            for (int nt = 0; nt < 4; nt++)
                #pragma unroll
                for (int r = 0; r < 4; r++) d[mt][nt][r] = 0.f;

        #pragma unroll
        for (int tap = 0; tap < 2; tap++) {
            const uint32_t aE0 = sb + E_OFF + ab0 + tap * RSE;
            const uint32_t aE1 = sb + E_OFF + ab1 + tap * RSE;
            const uint32_t bW0 = sb + W_OFF + tap * 9216 + bb0;
            const uint32_t bW1 = sb + W_OFF + tap * 9216 + bb1;
            #pragma unroll
            for (int ks = 0; ks < 4; ks++) {
                const uint32_t kb = ks * 32;
                uint32_t a0[4], a1[4], b0[4], b1[4];
                LDMX4(a0, aE0 + kb);
                LDMX4(a1, aE1 + kb);
                LDMX4(b0, bW0 + kb);
                LDMX4(b1, bW1 + kb);
                MMA(d[0][0], a0, b0[0], b0[1]);
                MMA(d[0][1], a0, b0[2], b0[3]);
                MMA(d[0][2], a0, b1[0], b1[1]);
                MMA(d[0][3], a0, b1[2], b1[3]);
                MMA(d[1][0], a1, b0[0], b0[1]);
                MMA(d[1][1], a1, b0[2], b0[3]);
                MMA(d[1][2], a1, b1[0], b1[1]);
                MMA(d[1][3], a1, b1[2], b1[3]);
            }
        }

        // ---- 4. warp-local max over 32 m-rows -> red[par][wid] ----
        #pragma unroll
        for (int nt = 0; nt < 4; nt++) {
            float v0 = fmaxf(fmaxf(d[0][nt][0], d[0][nt][2]),
                             fmaxf(d[1][nt][0], d[1][nt][2]));
            float v1 = fmaxf(fmaxf(d[0][nt][1], d[0][nt][3]),
                             fmaxf(d[1][nt][1], d[1][nt][3]));
            #pragma unroll
            for (int mask = 4; mask <= 16; mask <<= 1) {
                v0 = fmaxf(v0, __shfl_xor_sync(0xffffffffu, v0, mask));
                v1 = fmaxf(v1, __shfl_xor_sync(0xffffffffu, v1, mask));
            }
            if (lane < 4) {
                red[par][wid][nt * 8 + lane * 2]     = v0;
                red[par][wid][nt * 8 + lane * 2 + 1] = v1;
            }
        }
        __syncthreads();   // MMA E-reads + red writes complete

        // ---- 5. pack + STS next tile's E (overwrites in place) ----
        if (nx) {
            #pragma unroll
            for (int g = 0; g < 10; g++) {
                int k = tid + g * 256, row = k >> 4, q = k & 15;
                int a = (row % 80) / 5;
                *reinterpret_cast<u64*>(smem + E_OFF + row * RSE + ((a & 1) << 4) + q * 8)
                    = pack4(v[g].x, v[g].y, v[g].z, v[g].w);
            }
        }
        if (tid < 160 && nx2) idx_s[tid] = ridx;

        // ---- 6. store this tile's output ----
        if (tid < 128) {
            int b2 = tid >> 6, c = tid & 63, ch = c >> 5, cc = c & 31;
            int w1 = ch * 4 + b2 * 2;
            float m = fmaxf(red[par][w1][cc], red[par][w1 + 1][cc]);
            out[(long long)(tile * 2 + b2) * 64 + c] = m + __ldg(&conv_b[c]);
        }
        par ^= 1;
        __syncthreads();   // E/idx stores visible before next MMA
    }
}

extern "C" void kernel_launch(void* const* d_in, const int* in_sizes, int n_in,
                              void* d_out, int out_size) {
    const int*   path_input = (const int*)d_in[0];
    const int*   path_type  = (const int*)d_in[1];
    const float* tables     = (const float*)d_in[2];
    const float* conv_w     = (const float*)d_in[3];
    const float* conv_b     = (const float*)d_in[4];
    float* out = (float*)d_out;

    cudaFuncSetAttribute(path_emb_hmma,
                         cudaFuncAttributeMaxDynamicSharedMemorySize, SM_TOT);

    path_emb_hmma<<<NPERS, 256, SM_TOT>>>(path_input, path_type, tables,
                                          conv_w, conv_b, out);
}

// round 10
// speedup vs baseline: 1.5264x; 1.3184x over previous
#include <cuda_runtime.h>
#include <cuda_fp16.h>
#include <cstdint>

// Path_Embedding via mma.sync m16n8k16.f16, single-f16 operands.
// Round 10: double-buffered E (direct LDG->pack->STS.128 gather, no register
// holding), ONE barrier per tile, tile-invariant gather addressing hoisted.
// Persistent 444 blocks (3/SM).

#define VOCAB 100000
#define NPERS 444
#define RSE 160        // e-row stride bytes (+16B nudge when a odd)
#define RSW 144        // w-row stride bytes (+16B nudge when (o>>3)&1)

#define E0_OFF  0      // 160*160 = 25600
#define E1_OFF  25600
#define W_OFF   51200  // 2 taps * 64 * 144 = 18432
#define IDX_OFF 69632  // 2*160*4 = 1280
#define RED_OFF 70912  // 2*8*32*4 = 2048
#define SM_TOT  72960

typedef unsigned long long u64;

__device__ __forceinline__ uint32_t smem_u32(const void* p) {
    uint32_t a;
    asm("{ .reg .u64 t; cvta.to.shared.u64 t, %1; cvt.u32.u64 %0, t; }" : "=r"(a) : "l"(p));
    return a;
}

#define LDMX4(r, addr)                                                        \
    asm volatile("ldmatrix.sync.aligned.m8n8.x4.shared.b16 {%0,%1,%2,%3}, [%4];" \
        : "=r"((r)[0]), "=r"((r)[1]), "=r"((r)[2]), "=r"((r)[3]) : "r"(addr))

#define MMA(d, a, b0, b1)                                                     \
    asm volatile("mma.sync.aligned.m16n8k16.row.col.f32.f16.f16.f32 "         \
        "{%0,%1,%2,%3},{%4,%5,%6,%7},{%8,%9},{%0,%1,%2,%3};"                  \
        : "+f"((d)[0]), "+f"((d)[1]), "+f"((d)[2]), "+f"((d)[3])              \
        : "r"((a)[0]), "r"((a)[1]), "r"((a)[2]), "r"((a)[3]),                 \
          "r"(b0), "r"(b1))

__device__ __forceinline__ u64 pack4(float x, float y, float z, float w) {
    __half2 h01 = __float22half2_rn(make_float2(x, y));
    __half2 h23 = __float22half2_rn(make_float2(z, w));
    uint32_t h0 = *reinterpret_cast<uint32_t*>(&h01);
    uint32_t h1 = *reinterpret_cast<uint32_t*>(&h23);
    return (u64)h0 | ((u64)h1 << 32);
}

__global__ __launch_bounds__(256, 3) void path_emb_hmma(
    const int*   __restrict__ path_input,   // [8192,16,5]
    const int*   __restrict__ path_type,    // [5]
    const float* __restrict__ tables,       // [3,100000,64]
    const float* __restrict__ conv_w,       // [64,64,2]
    const float* __restrict__ conv_b,       // [64]
    float*       __restrict__ out)          // [8192,64]
{
    extern __shared__ char smem[];
    const uint32_t sb = smem_u32(smem);
    const int tid  = threadIdx.x;
    const int lane = tid & 31;
    const int wid  = tid >> 5;
    const int mgrp = wid & 3;
    const int ngrp = wid >> 2;

    int (*idx_s)[160]   = reinterpret_cast<int(*)[160]>(smem + IDX_OFF);
    float (*red)[8][32] = reinterpret_cast<float(*)[8][32]>(smem + RED_OFF);
    const float4* tab4  = reinterpret_cast<const float4*>(tables);

    // ---- stage W once per block ----
    {
        const float2* cw2 = reinterpret_cast<const float2*>(conv_w);
        #pragma unroll
        for (int it = 0; it < 16; it++) {
            int i = tid + it * 256;          // i = o*64 + j
            int o = i >> 6, j = i & 63;
            float2 wv = cw2[i];
            int ob = o * RSW + (((o >> 3) & 1) << 4) + j * 2;
            *reinterpret_cast<__half*>(smem + W_OFF + ob)        = __float2half_rn(wv.x);
            *reinterpret_cast<__half*>(smem + W_OFF + 9216 + ob) = __float2half_rn(wv.y);
        }
    }

    // ---- tile-invariant gather addressing: thread covers rows k>>3, q-pair k&7 ----
    int      grow[5];
    uint32_t goff[5];
    #pragma unroll
    for (int g = 0; g < 5; g++) {
        int k = tid + g * 256;               // 1280 = 160 rows * 8 q-pairs
        int row = k >> 3, qq = k & 7;
        int a = (row % 80) / 5;
        grow[g] = row;
        goff[g] = (uint32_t)(row * RSE + ((a & 1) << 4) + qq * 16);
    }

    // ---- tile-invariant idx-staging params (tid < 160) ----
    int ib_a = 0, ib_t = 0, ib_base = 0, ib_type = 0;
    if (tid < 160) {
        int b2 = tid / 80, rr = tid % 80;
        ib_a = rr / 5; ib_t = rr % 5;
        ib_base = b2;                         // b = tile*2 + b2
        ib_type = __ldg(&path_type[ib_t]) * VOCAB;
    }

    // ---- tile-invariant epilogue params (tid < 128) ----
    float bias = 0.f; int ob2 = 0, oc = 0, ow1 = 0, occ_ = 0;
    if (tid < 128) {
        ob2 = tid >> 6; oc = tid & 63;
        ow1 = (oc >> 5) * 4 + ob2 * 2; occ_ = oc & 31;
        bias = __ldg(&conv_b[oc]);
    }

    // ---- ldmatrix lane addresses (tile-invariant, relative to E base) ----
    uint32_t ab0, ab1, bb0, bb1;
    {
        int m  = mgrp * 32 + (lane & 15);
        int b2 = mgrp >> 1;
        int aa = (m >> 2) & 15, w = m & 3;
        ab0 = (uint32_t)((b2 * 80 + aa * 5 + w) * RSE + ((aa & 1) << 4)
                         + ((lane >> 4) << 4));
        int m1 = m + 16;
        int aa1 = (m1 >> 2) & 15, w1 = m1 & 3;
        ab1 = (uint32_t)((b2 * 80 + aa1 * 5 + w1) * RSE + ((aa1 & 1) << 4)
                         + ((lane >> 4) << 4));
        int nr = ngrp * 32 + (lane & 7) + ((lane >> 4) << 3);
        bb0 = (uint32_t)(nr * RSW + (((nr >> 3) & 1) << 4) + (((lane >> 3) & 1) << 4));
        int nr1 = nr + 16;
        bb1 = (uint32_t)(nr1 * RSW + (((nr1 >> 3) & 1) << 4) + (((lane >> 3) & 1) << 4));
    }

    // ---- prologue: idx[0](tile0) -> gather E[0] ; idx[1](tile0+NPERS) ----
    const int tile0 = blockIdx.x;
    if (tid < 160)
        idx_s[0][tid] = ib_type
            + path_input[(((ib_a << 9) + tile0 * 2 + ib_base) * 16
                          + ((tile0 * 2 + ib_base) & 15) * 0) * 0];  // placeholder (recomputed below)
    // NOTE: correct staging below (kept explicit for clarity)
    if (tid < 160) {
        int b = tile0 * 2 + ib_base, p = b & 15, nb = b >> 4;
        idx_s[0][tid] = ib_type + path_input[(((ib_a << 9) + nb) * 16 + p) * 5 + ib_t];
    }
    __syncthreads();
    #pragma unroll
    for (int g = 0; g < 5; g++) {
        long long base = (long long)idx_s[0][grow[g]] * 16 + ((goff[g] >> 3) & 7) * 0;
        int qq = (tid + g * 256) & 7;
        float4 va = __ldg(&tab4[(long long)idx_s[0][grow[g]] * 16 + qq * 2]);
        float4 vb = __ldg(&tab4[(long long)idx_s[0][grow[g]] * 16 + qq * 2 + 1]);
        (void)base;
        ulonglong2 hv; hv.x = pack4(va.x, va.y, va.z, va.w);
        hv.y = pack4(vb.x, vb.y, vb.z, vb.w);
        *reinterpret_cast<ulonglong2*>(smem + E0_OFF + goff[g]) = hv;
    }
    if (tid < 160 && tile0 + NPERS < 4096) {
        int b = (tile0 + NPERS) * 2 + ib_base, p = b & 15, nb = b >> 4;
        idx_s[1][tid] = ib_type + path_input[(((ib_a << 9) + nb) * 16 + p) * 5 + ib_t];
    }
    __syncthreads();

    int n = 0;
    for (int tile = tile0; tile < 4096; tile += NPERS, n++) {
        const int  fr  = n & 1;               // front E/idx/red buffer
        const int  bk  = fr ^ 1;
        const bool nx  = tile + NPERS     < 4096;
        const bool nx2 = tile + 2 * NPERS < 4096;
        const uint32_t eF = fr ? E1_OFF : E0_OFF;
        const uint32_t eB = fr ? E0_OFF : E1_OFF;

        // ---- gather next tile directly into back E buffer ----
        if (nx) {
            #pragma unroll
            for (int g = 0; g < 5; g++) {
                int qq = (tid + g * 256) & 7;
                long long rbase = (long long)idx_s[bk][grow[g]] * 16 + qq * 2;
                float4 va = __ldg(&tab4[rbase]);
                float4 vb = __ldg(&tab4[rbase + 1]);
                ulonglong2 hv;
                hv.x = pack4(va.x, va.y, va.z, va.w);
                hv.y = pack4(vb.x, vb.y, vb.z, vb.w);
                *reinterpret_cast<ulonglong2*>(smem + eB + goff[g]) = hv;
            }
        }
        // ---- prefetch idx(tile + 2*NPERS) into a register ----
        int ridx = 0;
        if (tid < 160 && nx2) {
            int b = (tile + 2 * NPERS) * 2 + ib_base, p = b & 15, nb = b >> 4;
            ridx = ib_type + path_input[(((ib_a << 9) + nb) * 16 + p) * 5 + ib_t];
        }

        // ---- MMA on front E ----
        float d[2][4][4];
        #pragma unroll
        for (int mt = 0; mt < 2; mt++)
            #pragma unroll
            for (int nt = 0; nt < 4; nt++)
                #pragma unroll
                for (int r = 0; r < 4; r++) d[mt][nt][r] = 0.f;

        #pragma unroll
        for (int tap = 0; tap < 2; tap++) {
            const uint32_t aE0 = sb + eF + ab0 + tap * RSE;
            const uint32_t aE1 = sb + eF + ab1 + tap * RSE;
            const uint32_t bW0 = sb + W_OFF + tap * 9216 + bb0;
            const uint32_t bW1 = sb + W_OFF + tap * 9216 + bb1;
            #pragma unroll
            for (int ks = 0; ks < 4; ks++) {
                const uint32_t kb = ks * 32;
                uint32_t a0[4], a1[4], b0[4], b1[4];
                LDMX4(a0, aE0 + kb);
                LDMX4(a1, aE1 + kb);
                LDMX4(b0, bW0 + kb);
                LDMX4(b1, bW1 + kb);
                MMA(d[0][0], a0, b0[0], b0[1]);
                MMA(d[0][1], a0, b0[2], b0[3]);
                MMA(d[0][2], a0, b1[0], b1[1]);
                MMA(d[0][3], a0, b1[2], b1[3]);
                MMA(d[1][0], a1, b0[0], b0[1]);
                MMA(d[1][1], a1, b0[2], b0[3]);
                MMA(d[1][2], a1, b1[0], b1[1]);
                MMA(d[1][3], a1, b1[2], b1[3]);
            }
        }

        // ---- warp-local max over 32 m-rows -> red[fr][wid] ----
        #pragma unroll
        for (int nt = 0; nt < 4; nt++) {
            float v0 = fmaxf(fmaxf(d[0][nt][0], d[0][nt][2]),
                             fmaxf(d[1][nt][0], d[1][nt][2]));
            float v1 = fmaxf(fmaxf(d[0][nt][1], d[0][nt][3]),
                             fmaxf(d[1][nt][1], d[1][nt][3]));
            #pragma unroll
            for (int mask = 4; mask <= 16; mask <<= 1) {
                v0 = fmaxf(v0, __shfl_xor_sync(0xffffffffu, v0, mask));
                v1 = fmaxf(v1, __shfl_xor_sync(0xffffffffu, v1, mask));
            }
            if (lane < 4) {
                red[fr][wid][nt * 8 + lane * 2]     = v0;
                red[fr][wid][nt * 8 + lane * 2 + 1] = v1;
            }
        }
        // ---- stage idx(tile+2*NPERS) into idx[fr] (pre-sync) ----
        if (tid < 160 && nx2) idx_s[fr][tid] = ridx;

        __syncthreads();

        // ---- store this tile's output (reads red[fr] post-sync) ----
        if (tid < 128) {
            float m = fmaxf(red[fr][ow1][occ_], red[fr][ow1 + 1][occ_]);
            out[(long long)(tile * 2 + ob2) * 64 + oc] = m + bias;
        }
    }
}

extern "C" void kernel_launch(void* const* d_in, const int* in_sizes, int n_in,
                              void* d_out, int out_size) {
    const int*   path_input = (const int*)d_in[0];
    const int*   path_type  = (const int*)d_in[1];
    const float* tables     = (const float*)d_in[2];
    const float* conv_w     = (const float*)d_in[3];
    const float* conv_b     = (const float*)d_in[4];
    float* out = (float*)d_out;

    cudaFuncSetAttribute(path_emb_hmma,
                         cudaFuncAttributeMaxDynamicSharedMemorySize, SM_TOT);

    path_emb_hmma<<<NPERS, 256, SM_TOT>>>(path_input, path_type, tables,
                                          conv_w, conv_b, out);
}